// round 2
// baseline (speedup 1.0000x reference)
#include <cuda_runtime.h>
#include <cstdint>

// Haar inverse DWT2 (db1), fp32.  Inputs A,H,V,D: [8,32,256,256]; out: [8,32,512,512].
// x[2i,2j]=(A+H+V+D)/2; x[2i,2j+1]=(A+H-V-D)/2; x[2i+1,2j]=(A-H+V-D)/2; x[2i+1,2j+1]=(A-H-V+D)/2
//
// R2: one thread per float4 of input (4 consecutive j). 16B loads x4 inputs,
// 4x STG.128 (two consecutive per output row). Streaming hints (__ldcs/__stcs):
// all streams are touch-once, mark evict-first to minimize L2 thrash.

__global__ void __launch_bounds__(256) idwt2_haar_kernel(
    const float4* __restrict__ A,
    const float4* __restrict__ H,
    const float4* __restrict__ V,
    const float4* __restrict__ D,
    float4* __restrict__ out)
{
    // total threads = 8*32*256*256 / 4 = 4,194,304
    const unsigned t = blockIdx.x * 256u + threadIdx.x;

    const float4 a = __ldcs(&A[t]);
    const float4 h = __ldcs(&H[t]);
    const float4 v = __ldcs(&V[t]);
    const float4 d = __ldcs(&D[t]);

    // per-element butterflies
    float lp0 = a.x + h.x, lm0 = a.x - h.x, mp0 = v.x + d.x, mm0 = v.x - d.x;
    float lp1 = a.y + h.y, lm1 = a.y - h.y, mp1 = v.y + d.y, mm1 = v.y - d.y;
    float lp2 = a.z + h.z, lm2 = a.z - h.z, mp2 = v.z + d.z, mm2 = v.z - d.z;
    float lp3 = a.w + h.w, lm3 = a.w - h.w, mp3 = v.w + d.w, mm3 = v.w - d.w;

    float4 e0, e1, o0, o1;
    e0.x = (lp0 + mp0) * 0.5f;  e0.y = (lp0 - mp0) * 0.5f;
    e0.z = (lp1 + mp1) * 0.5f;  e0.w = (lp1 - mp1) * 0.5f;
    e1.x = (lp2 + mp2) * 0.5f;  e1.y = (lp2 - mp2) * 0.5f;
    e1.z = (lp3 + mp3) * 0.5f;  e1.w = (lp3 - mp3) * 0.5f;
    o0.x = (lm0 + mm0) * 0.5f;  o0.y = (lm0 - mm0) * 0.5f;
    o0.z = (lm1 + mm1) * 0.5f;  o0.w = (lm1 - mm1) * 0.5f;
    o1.x = (lm2 + mm2) * 0.5f;  o1.y = (lm2 - mm2) * 0.5f;
    o1.z = (lm3 + mm3) * 0.5f;  o1.w = (lm3 - mm3) * 0.5f;

    // t = b*16384 + i*64 + j4   (b in [0,256), i in [0,256), j4 in [0,64))
    // even-row out f4 index = b*65536 + (2i)*128 + 2*j4 = ((t>>6)<<8) + 2*(t&63)
    const unsigned o = ((t >> 6) << 8) + ((t & 63u) << 1);
    __stcs(&out[o],        e0);
    __stcs(&out[o + 1u],   e1);
    __stcs(&out[o + 128u], o0);   // odd row: +512 floats = +128 float4s
    __stcs(&out[o + 129u], o1);
}

extern "C" void kernel_launch(void* const* d_in, const int* in_sizes, int n_in,
                              void* d_out, int out_size)
{
    const float4* A = (const float4*)d_in[0];
    const float4* H = (const float4*)d_in[1];
    const float4* V = (const float4*)d_in[2];
    const float4* D = (const float4*)d_in[3];
    float4* out = (float4*)d_out;

    const unsigned n_threads = (unsigned)(in_sizes[0] / 4);
    const unsigned blocks = (n_threads + 255u) / 256u;

    idwt2_haar_kernel<<<blocks, 256>>>(A, H, V, D, out);
}

// round 3
// speedup vs baseline: 1.0504x; 1.0504x over previous
#include <cuda_runtime.h>
#include <cstdint>

// Haar inverse DWT2 (db1), fp32.  Inputs A,H,V,D: [8,32,256,256]; out: [8,32,512,512].
// x[2i,2j]=(A+H+V+D)/2; x[2i,2j+1]=(A+H-V-D)/2; x[2i+1,2j]=(A-H+V-D)/2; x[2i+1,2j+1]=(A-H-V+D)/2
//
// R3: champion R1 structure (one thread per float2; two STG.128 per thread;
// max thread count for latency hiding) + single change: __stcs on stores so the
// write-once output stream is marked evict-first in L2.

__global__ void __launch_bounds__(256) idwt2_haar_kernel(
    const float2* __restrict__ A,
    const float2* __restrict__ H,
    const float2* __restrict__ V,
    const float2* __restrict__ D,
    float4* __restrict__ out)
{
    // total threads = 8*32*256*256 / 2 = 8,388,608
    const unsigned t = blockIdx.x * 256u + threadIdx.x;

    const float2 a = __ldg(&A[t]);
    const float2 h = __ldg(&H[t]);
    const float2 v = __ldg(&V[t]);
    const float2 d = __ldg(&D[t]);

    float lp0 = a.x + h.x, lm0 = a.x - h.x;
    float mp0 = v.x + d.x, mm0 = v.x - d.x;
    float lp1 = a.y + h.y, lm1 = a.y - h.y;
    float mp1 = v.y + d.y, mm1 = v.y - d.y;

    float4 even, odd;
    even.x = (lp0 + mp0) * 0.5f;
    even.y = (lp0 - mp0) * 0.5f;
    even.z = (lp1 + mp1) * 0.5f;
    even.w = (lp1 - mp1) * 0.5f;
    odd.x  = (lm0 + mm0) * 0.5f;
    odd.y  = (lm0 - mm0) * 0.5f;
    odd.z  = (lm1 + mm1) * 0.5f;
    odd.w  = (lm1 - mm1) * 0.5f;

    // t = b*32768 + i*128 + j2 ; even-row out f4 index = ((t>>7)<<8) + (t&127)
    const unsigned o = ((t >> 7) << 8) + (t & 127u);
    __stcs(&out[o],        even);
    __stcs(&out[o + 128u], odd);   // odd row: +512 floats = +128 float4s
}

extern "C" void kernel_launch(void* const* d_in, const int* in_sizes, int n_in,
                              void* d_out, int out_size)
{
    const float2* A = (const float2*)d_in[0];
    const float2* H = (const float2*)d_in[1];
    const float2* V = (const float2*)d_in[2];
    const float2* D = (const float2*)d_in[3];
    float4* out = (float4*)d_out;

    const unsigned n_threads = (unsigned)(in_sizes[0] / 2);
    const unsigned blocks = (n_threads + 255u) / 256u;

    idwt2_haar_kernel<<<blocks, 256>>>(A, H, V, D, out);
}

// round 4
// speedup vs baseline: 1.0709x; 1.0195x over previous
#include <cuda_runtime.h>
#include <cstdint>

// Haar inverse DWT2 (db1), fp32.  Inputs A,H,V,D: [8,32,256,256]; out: [8,32,512,512].
// x[2i,2j]=(A+H+V+D)/2; x[2i,2j+1]=(A+H-V-D)/2; x[2i+1,2j]=(A-H+V-D)/2; x[2i+1,2j+1]=(A-H-V+D)/2
//
// R4: exact R1 champion dataflow (one thread per float2, two STG.128, 18 regs,
// plain __ldg loads / plain stores — .cs hints measured neutral) with block=512:
// each block spans 16KB contiguous output + 4KB contiguous reads per stream,
// for longer same-page DRAM bursts per scheduling unit.

__global__ void __launch_bounds__(512) idwt2_haar_kernel(
    const float2* __restrict__ A,
    const float2* __restrict__ H,
    const float2* __restrict__ V,
    const float2* __restrict__ D,
    float4* __restrict__ out)
{
    // total threads = 8*32*256*256 / 2 = 8,388,608
    const unsigned t = blockIdx.x * 512u + threadIdx.x;

    const float2 a = __ldg(&A[t]);
    const float2 h = __ldg(&H[t]);
    const float2 v = __ldg(&V[t]);
    const float2 d = __ldg(&D[t]);

    float lp0 = a.x + h.x, lm0 = a.x - h.x;
    float mp0 = v.x + d.x, mm0 = v.x - d.x;
    float lp1 = a.y + h.y, lm1 = a.y - h.y;
    float mp1 = v.y + d.y, mm1 = v.y - d.y;

    float4 even, odd;
    even.x = (lp0 + mp0) * 0.5f;
    even.y = (lp0 - mp0) * 0.5f;
    even.z = (lp1 + mp1) * 0.5f;
    even.w = (lp1 - mp1) * 0.5f;
    odd.x  = (lm0 + mm0) * 0.5f;
    odd.y  = (lm0 - mm0) * 0.5f;
    odd.z  = (lm1 + mm1) * 0.5f;
    odd.w  = (lm1 - mm1) * 0.5f;

    // t = b*32768 + i*128 + j2 ; even-row out f4 index = ((t>>7)<<8) + (t&127)
    const unsigned o = ((t >> 7) << 8) + (t & 127u);
    out[o]        = even;
    out[o + 128u] = odd;   // odd row: +512 floats = +128 float4s
}

extern "C" void kernel_launch(void* const* d_in, const int* in_sizes, int n_in,
                              void* d_out, int out_size)
{
    const float2* A = (const float2*)d_in[0];
    const float2* H = (const float2*)d_in[1];
    const float2* V = (const float2*)d_in[2];
    const float2* D = (const float2*)d_in[3];
    float4* out = (float4*)d_out;

    const unsigned n_threads = (unsigned)(in_sizes[0] / 2);
    const unsigned blocks = (n_threads + 511u) / 512u;

    idwt2_haar_kernel<<<blocks, 512>>>(A, H, V, D, out);
}